// round 5
// baseline (speedup 1.0000x reference)
#include <cuda_runtime.h>
#include <cuda_bf16.h>
#include <cstdint>

// Problem constants (fixed by the dataset)
#define B_  8
#define S_  4096
#define D_  1024
#define H_  16
#define HD_ 64
#define NR_ 32
#define ROWS_ (B_ * S_ * H_)        // 524288
#define TILE 64                      // rows per tile
#define NT   (ROWS_ / TILE)          // 8192 tiles
#define GRID 912                     // 152 SMs x 6 blocks (GB300)
#define TPB  128
#define PITCH 69                     // bank multiplier 5 (odd)

// per-row-class pad before columns >= 32: b = {3,1,2,2} (verified conflict-free
// for Givens uniform-column access and the remix read pattern at multiplier 5)
__device__ __forceinline__ int bpad(int p) { return (0x2213 >> (p * 4)) & 0xF; }

__device__ __forceinline__ void cp_async4(uint32_t saddr, const float* g) {
    asm volatile("cp.async.ca.shared.global [%0], [%1], 4;" :: "r"(saddr), "l"(g));
}
__device__ __forceinline__ void cp_commit() { asm volatile("cp.async.commit_group;"); }
__device__ __forceinline__ void cp_wait1()  { asm volatile("cp.async.wait_group 1;"); }
__device__ __forceinline__ void cp_wait0()  { asm volatile("cp.async.wait_group 0;"); }

// ---------------------------------------------------------------------------
__global__ __launch_bounds__(TPB, 6)
void rotary_pipe_kernel(const float* __restrict__ x,
                        const float* __restrict__ thetas,
                        const float* __restrict__ r_pairs,
                        const float* __restrict__ theta_scale,
                        const float* __restrict__ inv_freq,
                        const float* __restrict__ r_matrix,
                        float* __restrict__ out) {
    __shared__ float sm[2][TILE * PITCH];                 // 35,328 B
    __shared__ __align__(16) float tabc[2][4 * NR_];      // 1 KB
    __shared__ __align__(16) float tabs[2][4 * NR_];      // 1 KB
    __shared__ float2 scs[NR_];                           // 256 B
    __shared__ int    oij[NR_ * 4];                       // [k*4 + class], 512 B
    __shared__ float  sif[NR_];                           // 128 B

    const int t = threadIdx.x;

    // ---- once-per-block prologue: params + identity check -----------------
    if (t < NR_) sif[t] = inv_freq[t];
    {
        int k = t & 31, p = t >> 5;                      // 128 threads: 4 classes x 32
        float th = thetas[k] * theta_scale[0];
        float sv, cv;
        sincosf(th, &sv, &cv);
        int i = (int)r_pairs[2 * k];
        int j = (int)r_pairs[2 * k + 1];
        if (i < 0) i = 0; if (i > HD_ - 1) i = HD_ - 1;
        if (j < 0) j = 0; if (j > HD_ - 1) j = HD_ - 1;
        if (i == j) sv = 0.0f;                           // makes general form exact
        if (p == 0) scs[k] = make_float2(cv, sv);
        int oi = i + ((i >= 32) ? bpad(p) : 0);
        int oj = j + ((j >= 32) ? bpad(p) : 0);
        oij[k * 4 + p] = oi | (oj << 16);
    }
    int ok = 1;
    {
        const float4* rm4 = (const float4*)r_matrix;
        #pragma unroll
        for (int k = 0; k < 8; k++) {
            int q = k * TPB + t;
            float4 v = rm4[q];
            int e = q * 4;
            ok &= (v.x == (((e + 0) >> 6) == ((e + 0) & 63) ? 1.0f : 0.0f));
            ok &= (v.y == (((e + 1) >> 6) == ((e + 1) & 63) ? 1.0f : 0.0f));
            ok &= (v.z == (((e + 2) >> 6) == ((e + 2) & 63) ? 1.0f : 0.0f));
            ok &= (v.w == (((e + 3) >> 6) == ((e + 3) & 63) ? 1.0f : 0.0f));
        }
    }
    const int identity = __syncthreads_and(ok);          // barrier covers param writes

    // ---- stage-in constants (thread-invariant across tiles) ----------------
    const int c_in  = t & 63;                            // column this thread copies
    const int r0_in = t >> 6;                            // 0 or 1
    const int wA = c_in + ((c_in >= 32) ? bpad(r0_in & 3) : 0);        // k even
    const int wB = c_in + ((c_in >= 32) ? bpad((r0_in + 2) & 3) : 0);  // k odd

    // remix constants
    const int jj = t & 7;
    const int rs = t >> 3;                               // 0..15
    const int off0 = 8 * jj + ((jj >= 4) ? bpad(rs & 3) : 0);

    // ---- prologue of the pipeline: load tile T0 ---------------------------
    int T = blockIdx.x;
    {
        const float* g = x + (long long)T * (TILE * HD_) + t;
        #pragma unroll
        for (int k = 0; k < 16; k++) {                   // pairs (2k, 2k+1)
            int rA = r0_in + 4 * k;
            cp_async4((uint32_t)__cvta_generic_to_shared(&sm[0][rA * PITCH + wA]),
                      g + 256 * k);
            cp_async4((uint32_t)__cvta_generic_to_shared(&sm[0][(rA + 2) * PITCH + wB]),
                      g + 256 * k + 128);
        }
        cp_commit();
        // RoPE table for tile T0
        int gg = t >> 5, k = t & 31;
        int s = (4 * T + gg) & (S_ - 1);
        float a = (float)s * sif[k];
        float sv, cv;
        sincosf(a, &sv, &cv);
        tabc[0][gg * 32 + k] = cv;
        tabs[0][gg * 32 + k] = sv;
    }

    // ---- main pipelined loop ----------------------------------------------
    int cur = 0;
    for (; T < NT; T += GRID, cur ^= 1) {
        int Tn = T + GRID;
        __syncthreads();                 // prior remix reads of sm[cur^1]/tab[cur^1] done
        if (Tn < NT) {
            const float* g = x + (long long)Tn * (TILE * HD_) + t;
            float* buf = sm[cur ^ 1];
            #pragma unroll
            for (int k = 0; k < 16; k++) {
                int rA = r0_in + 4 * k;
                cp_async4((uint32_t)__cvta_generic_to_shared(&buf[rA * PITCH + wA]),
                          g + 256 * k);
                cp_async4((uint32_t)__cvta_generic_to_shared(&buf[(rA + 2) * PITCH + wB]),
                          g + 256 * k + 128);
            }
            cp_commit();
            int gg = t >> 5, k = t & 31;
            int s = (4 * Tn + gg) & (S_ - 1);
            float a = (float)s * sif[k];
            float sv, cv;
            sincosf(a, &sv, &cv);
            tabc[cur ^ 1][gg * 32 + k] = cv;
            tabs[cur ^ 1][gg * 32 + k] = sv;
            cp_wait1();                  // tile T arrived (Tn still in flight)
        } else {
            cp_wait0();
        }
        __syncthreads();                 // sm[cur] visible to all threads

        // ---- Givens chain: thread per row (threads 0..63) -----------------
        if (t < TILE) {
            float* row = &sm[cur][t * PITCH];
            const int p4 = t & 3;
            #pragma unroll
            for (int k = 0; k < NR_; k++) {
                float2 cs = scs[k];
                int pk = oij[k * 4 + p4];
                int oi = pk & 0xFFFF, oj = pk >> 16;
                float xi = row[oi];
                float xj = row[oj];
                row[oi] = fmaf(xi, cs.x, xj * cs.y);
                row[oj] = fmaf(xj, cs.x, -xi * cs.y);
            }
            // general path: dense r_matrix multiply (not taken when identity)
            if (!identity) {
                const int bp = bpad(p4);
                float y[HD_];
                for (int c2 = 0; c2 < HD_; c2++) {
                    float acc = 0.0f;
                    for (int k = 0; k < HD_; k++) {
                        int ow = k + ((k >= 32) ? bp : 0);
                        acc = fmaf(row[ow], __ldg(&r_matrix[k * HD_ + c2]), acc);
                    }
                    y[c2] = acc;
                }
                for (int c2 = 0; c2 < HD_; c2++)
                    row[c2 + ((c2 >= 32) ? bp : 0)] = y[c2];
            }
        }
        __syncthreads();

        // ---- fused RoPE remix + coalesced stage-out -----------------------
        {
            float4* o4 = (float4*)(out + (long long)T * (TILE * HD_));
            const float* tc = tabc[cur];
            const float* ts = tabs[cur];
            #pragma unroll
            for (int i = 0; i < 4; i++) {
                int r = rs + 16 * i;                     // s-group == i
                float4 cv = *(const float4*)&tc[i * 32 + 4 * jj];
                float4 sv = *(const float4*)&ts[i * 32 + 4 * jj];
                const float* row = &sm[cur][r * PITCH + off0];
                float a0 = row[0], b0 = row[1];
                float a1 = row[2], b1 = row[3];
                float a2 = row[4], b2 = row[5];
                float a3 = row[6], b3 = row[7];
                float4 lo, hi;
                lo.x = a0 * cv.x - b0 * sv.x;  hi.x = a0 * sv.x + b0 * cv.x;
                lo.y = a1 * cv.y - b1 * sv.y;  hi.y = a1 * sv.y + b1 * cv.y;
                lo.z = a2 * cv.z - b2 * sv.z;  hi.z = a2 * sv.z + b2 * cv.z;
                lo.w = a3 * cv.w - b3 * sv.w;  hi.w = a3 * sv.w + b3 * cv.w;
                o4[r * 16 + jj]     = lo;
                o4[r * 16 + 8 + jj] = hi;
            }
        }
    }
}

// ---------------------------------------------------------------------------
extern "C" void kernel_launch(void* const* d_in, const int* in_sizes, int n_in,
                              void* d_out, int out_size) {
    const float* x           = (const float*)d_in[0];
    const float* thetas      = (const float*)d_in[1];
    const float* r_pairs     = (const float*)d_in[2];
    const float* theta_scale = (const float*)d_in[3];
    // d_in[4] = n_rots_scale (unused by reference)
    const float* r_matrix    = (const float*)d_in[5];
    const float* inv_freq    = (const float*)d_in[6];
    float* out = (float*)d_out;

    rotary_pipe_kernel<<<GRID, TPB>>>(x, thetas, r_pairs, theta_scale,
                                      inv_freq, r_matrix, out);
}

// round 9
// speedup vs baseline: 1.1909x; 1.1909x over previous
#include <cuda_runtime.h>
#include <cuda_bf16.h>
#include <cstdint>

// Problem constants (fixed by the dataset)
#define B_  8
#define S_  4096
#define D_  1024
#define H_  16
#define HD_ 64
#define NR_ 32
#define ROWS_ (B_ * S_ * H_)        // 524288
#define WROWS 32                     // rows per WARP tile
#define NTILES (ROWS_ / WROWS)       // 16384
#define WARPS_PB 4
#define TPB 128
#define PITCH 69                     // bank multiplier 5 (odd)

// per-row-class pad before columns >= 32: b = {3,1,2,2}
// (verified conflict-free for stage-in class pairs (0,1)/(2,3), Givens
// uniform-column access at multiplier 5, and the remix read pattern)
__device__ __forceinline__ int bpad(int p) { return (0x2213 >> (p * 4)) & 0xF; }

__device__ __forceinline__ void cp_async4(uint32_t saddr, const float* g) {
    asm volatile("cp.async.ca.shared.global [%0], [%1], 4;" :: "r"(saddr), "l"(g));
}
__device__ __forceinline__ void cp_commit() { asm volatile("cp.async.commit_group;"); }
__device__ __forceinline__ void cp_wait0()  { asm volatile("cp.async.wait_group 0;"); }

// ---------------------------------------------------------------------------
// Warp-autonomous kernel: each warp owns one 32-row tile; no block barriers
// after the prologue, so resident warps free-run and overlap phases.
// ---------------------------------------------------------------------------
__global__ __launch_bounds__(TPB, 6)
void rotary_warp_kernel(const float* __restrict__ x,
                        const float* __restrict__ thetas,
                        const float* __restrict__ r_pairs,
                        const float* __restrict__ theta_scale,
                        const float* __restrict__ inv_freq,
                        const float* __restrict__ r_matrix,
                        float* __restrict__ out) {
    __shared__ float sm[WARPS_PB][WROWS * PITCH];        // 35,328 B
    __shared__ __align__(16) float tabc[WARPS_PB][2 * NR_]; // 1 KB
    __shared__ __align__(16) float tabs[WARPS_PB][2 * NR_]; // 1 KB
    __shared__ float2 scs[NR_];                           // 256 B
    __shared__ int    oij[NR_ * 4];                       // [k*4 + class]

    const int t = threadIdx.x;
    const int w = t >> 5;
    const int l = t & 31;

    // ---- once-per-block prologue: params + identity check -----------------
    {
        int k = l, p = w;                                // 4 classes x 32 rotations
        float th = thetas[k] * theta_scale[0];
        float sv, cv;
        sincosf(th, &sv, &cv);
        int i = (int)r_pairs[2 * k];
        int j = (int)r_pairs[2 * k + 1];
        if (i < 0) i = 0; if (i > HD_ - 1) i = HD_ - 1;
        if (j < 0) j = 0; if (j > HD_ - 1) j = HD_ - 1;
        if (i == j) sv = 0.0f;                           // makes general form exact
        if (p == 0) scs[k] = make_float2(cv, sv);
        int oi = i + ((i >= 32) ? bpad(p) : 0);
        int oj = j + ((j >= 32) ? bpad(p) : 0);
        oij[k * 4 + p] = oi | (oj << 16);
    }
    int ok = 1;
    {
        const float4* rm4 = (const float4*)r_matrix;
        #pragma unroll
        for (int k = 0; k < 8; k++) {
            int q = k * TPB + t;
            float4 v = rm4[q];
            int e = q * 4;
            ok &= (v.x == (((e + 0) >> 6) == ((e + 0) & 63) ? 1.0f : 0.0f));
            ok &= (v.y == (((e + 1) >> 6) == ((e + 1) & 63) ? 1.0f : 0.0f));
            ok &= (v.z == (((e + 2) >> 6) == ((e + 2) & 63) ? 1.0f : 0.0f));
            ok &= (v.w == (((e + 3) >> 6) == ((e + 3) & 63) ? 1.0f : 0.0f));
        }
    }
    const int identity = __syncthreads_and(ok);          // only block barrier
    const float invf = inv_freq[l];                      // per-lane register

    // ---- warp tile ---------------------------------------------------------
    const int tile = blockIdx.x * WARPS_PB + w;          // exact cover: 4096*4
    float* buf = sm[w];
    const float* gx = x + (size_t)tile * (WROWS * HD_);

    // stage-in: 32x64 floats via 64 scalar cp.async per lane-group
    // (q = l + 32*it -> rows {2it, 2it+1}: class pairs (0,1)/(2,3), clean)
    #pragma unroll
    for (int it = 0; it < 16; it++) {
        int q = l + 32 * it;
        int r = q >> 4;
        int c = (q & 15) * 4;
        int wo = r * PITCH + c + ((c >= 32) ? bpad(r & 3) : 0);
        uint32_t sa = (uint32_t)__cvta_generic_to_shared(&buf[wo]);
        const float* gp = gx + q * 4;
        cp_async4(sa + 0,  gp + 0);
        cp_async4(sa + 4,  gp + 1);
        cp_async4(sa + 8,  gp + 2);
        cp_async4(sa + 12, gp + 3);
    }
    cp_commit();

    // RoPE table for this tile's 2 s-positions (overlaps the async fill)
    {
        int s0 = (tile * 2) & (S_ - 1);                  // row/16 mod S
        #pragma unroll
        for (int g = 0; g < 2; g++) {
            float a = (float)(s0 + g) * invf;
            float sv, cv;
            sincosf(a, &sv, &cv);
            tabc[w][g * 32 + l] = cv;
            tabs[w][g * 32 + l] = sv;
        }
    }
    cp_wait0();
    __syncwarp();

    // ---- Givens chain: lane l owns row l ----------------------------------
    {
        float* row = &buf[l * PITCH];
        const int p4 = l & 3;
        #pragma unroll
        for (int k = 0; k < NR_; k++) {
            float2 cs = scs[k];
            int pk = oij[k * 4 + p4];
            int oi = pk & 0xFFFF, oj = pk >> 16;
            float xi = row[oi];
            float xj = row[oj];
            row[oi] = fmaf(xi, cs.x, xj * cs.y);
            row[oj] = fmaf(xj, cs.x, -xi * cs.y);
        }
        // general path: dense r_matrix multiply (not taken when identity)
        if (!identity) {
            const int bp = bpad(p4);
            float y[HD_];
            for (int c2 = 0; c2 < HD_; c2++) {
                float acc = 0.0f;
                for (int k = 0; k < HD_; k++) {
                    int ow = k + ((k >= 32) ? bp : 0);
                    acc = fmaf(row[ow], __ldg(&r_matrix[k * HD_ + c2]), acc);
                }
                y[c2] = acc;
            }
            for (int c2 = 0; c2 < HD_; c2++)
                row[c2 + ((c2 >= 32) ? bp : 0)] = y[c2];
        }
    }
    __syncwarp();

    // ---- fused RoPE remix + coalesced stage-out ---------------------------
    // lane (jj = l&7, rslot = l>>3) computes out[4jj..4jj+3] AND out[+32]
    // for rows r = rslot + 4i (row class == rslot; all banks distinct).
    {
        const int jj = l & 7;
        const int rslot = l >> 3;                        // 0..3
        const int off0 = 8 * jj + ((jj >= 4) ? bpad(rslot) : 0);
        float4* o4 = (float4*)(out + (size_t)tile * (WROWS * HD_));
        const float* tc = tabc[w];
        const float* ts = tabs[w];

        #pragma unroll
        for (int i = 0; i < 8; i++) {
            int r = rslot + 4 * i;
            int g = i >> 2;                              // s-group: r<16 ? 0 : 1
            float4 cv = *(const float4*)&tc[g * 32 + 4 * jj];
            float4 sv = *(const float4*)&ts[g * 32 + 4 * jj];
            const float* row = &buf[r * PITCH + off0];
            float a0 = row[0], b0 = row[1];
            float a1 = row[2], b1 = row[3];
            float a2 = row[4], b2 = row[5];
            float a3 = row[6], b3 = row[7];
            float4 lo, hi;
            lo.x = a0 * cv.x - b0 * sv.x;  hi.x = a0 * sv.x + b0 * cv.x;
            lo.y = a1 * cv.y - b1 * sv.y;  hi.y = a1 * sv.y + b1 * cv.y;
            lo.z = a2 * cv.z - b2 * sv.z;  hi.z = a2 * sv.z + b2 * cv.z;
            lo.w = a3 * cv.w - b3 * sv.w;  hi.w = a3 * sv.w + b3 * cv.w;
            o4[r * 16 + jj]     = lo;
            o4[r * 16 + 8 + jj] = hi;
        }
    }
}

// ---------------------------------------------------------------------------
extern "C" void kernel_launch(void* const* d_in, const int* in_sizes, int n_in,
                              void* d_out, int out_size) {
    const float* x           = (const float*)d_in[0];
    const float* thetas      = (const float*)d_in[1];
    const float* r_pairs     = (const float*)d_in[2];
    const float* theta_scale = (const float*)d_in[3];
    // d_in[4] = n_rots_scale (unused by reference)
    const float* r_matrix    = (const float*)d_in[5];
    const float* inv_freq    = (const float*)d_in[6];
    float* out = (float*)d_out;

    rotary_warp_kernel<<<NTILES / WARPS_PB, TPB>>>(x, thetas, r_pairs, theta_scale,
                                                   inv_freq, r_matrix, out);
}

// round 10
// speedup vs baseline: 1.1988x; 1.0066x over previous
#include <cuda_runtime.h>
#include <cuda_bf16.h>
#include <cstdint>

// Problem constants (fixed by the dataset)
#define B_  8
#define S_  4096
#define D_  1024
#define H_  16
#define HD_ 64
#define NR_ 32
#define ROWS_ (B_ * S_ * H_)        // 524288
#define WROWS 32                     // rows per WARP tile
#define NTILES (ROWS_ / WROWS)       // 16384
#define WARPS_PB 4
#define TPB 128
#define PITCH 69                     // bank multiplier 5 (odd)

// per-row-class pad before columns >= 32: b = {3,1,2,2}
// (verified conflict-free for stage-in class pairs (0,1)/(2,3), Givens
// uniform-column access at multiplier 5, and the remix read pattern)
__device__ __forceinline__ int bpad(int p) { return (0x2213 >> (p * 4)) & 0xF; }

// Precomputed RoPE table: per s, 32 cos then 32 sin (64 floats)
__device__ float g_tab[S_ * 64];

// ---------------------------------------------------------------------------
__global__ __launch_bounds__(256)
void table_kernel(const float* __restrict__ inv_freq) {
    int idx = blockIdx.x * 256 + threadIdx.x;        // [0, S_*32)
    if (idx < S_ * NR_) {
        int s = idx >> 5;
        int k = idx & 31;
        float a = (float)s * inv_freq[k];
        float sv, cv;
        sincosf(a, &sv, &cv);
        g_tab[s * 64 + k]      = cv;
        g_tab[s * 64 + 32 + k] = sv;
    }
}

// ---------------------------------------------------------------------------
// Warp-autonomous kernel: each warp owns one 32-row tile; no block barriers
// after the prologue, so resident warps free-run and overlap phases.
// ---------------------------------------------------------------------------
__global__ __launch_bounds__(TPB, 6)
void rotary_warp_kernel(const float* __restrict__ x,
                        const float* __restrict__ thetas,
                        const float* __restrict__ r_pairs,
                        const float* __restrict__ theta_scale,
                        const float* __restrict__ r_matrix,
                        float* __restrict__ out) {
    __shared__ float sm[WARPS_PB][WROWS * PITCH];        // 35,328 B
    __shared__ float2 scs[NR_];                           // 256 B
    __shared__ int    oij[NR_ * 4];                       // [k*4 + class]

    const int t = threadIdx.x;
    const int w = t >> 5;
    const int l = t & 31;

    // ---- once-per-block prologue: params + identity check -----------------
    {
        int k = l, p = w;                                // 4 classes x 32 rotations
        float th = thetas[k] * theta_scale[0];
        float sv, cv;
        sincosf(th, &sv, &cv);
        int i = (int)r_pairs[2 * k];
        int j = (int)r_pairs[2 * k + 1];
        if (i < 0) i = 0; if (i > HD_ - 1) i = HD_ - 1;
        if (j < 0) j = 0; if (j > HD_ - 1) j = HD_ - 1;
        if (i == j) sv = 0.0f;                           // makes general form exact
        if (p == 0) scs[k] = make_float2(cv, sv);
        int oi = i + ((i >= 32) ? bpad(p) : 0);
        int oj = j + ((j >= 32) ? bpad(p) : 0);
        oij[k * 4 + p] = oi | (oj << 16);
    }
    int ok = 1;
    {
        const float4* rm4 = (const float4*)r_matrix;
        #pragma unroll
        for (int k = 0; k < 8; k++) {
            int q = k * TPB + t;
            float4 v = rm4[q];
            int e = q * 4;
            ok &= (v.x == (((e + 0) >> 6) == ((e + 0) & 63) ? 1.0f : 0.0f));
            ok &= (v.y == (((e + 1) >> 6) == ((e + 1) & 63) ? 1.0f : 0.0f));
            ok &= (v.z == (((e + 2) >> 6) == ((e + 2) & 63) ? 1.0f : 0.0f));
            ok &= (v.w == (((e + 3) >> 6) == ((e + 3) & 63) ? 1.0f : 0.0f));
        }
    }
    const int identity = __syncthreads_and(ok);          // only block barrier

    // ---- warp tile ---------------------------------------------------------
    const int tile = blockIdx.x * WARPS_PB + w;          // exact cover
    float* buf = sm[w];
    const float4* gx4 = (const float4*)(x + (size_t)tile * (WROWS * HD_));

    // remix lane constants
    const int jj = l & 7;
    const int rslot = l >> 3;                            // 0..3
    const int off0 = 8 * jj + ((jj >= 4) ? bpad(rslot) : 0);

    // issue the 4 RoPE-table vector loads EARLY (L2 latency hidden by Givens)
    const int s0 = (tile * 2) & (S_ - 1);                // row/16 mod S
    const float4* tg = (const float4*)g_tab;             // 16 float4 per s
    float4 cv0 = tg[s0 * 16 + jj];
    float4 sv0 = tg[s0 * 16 + 8 + jj];
    float4 cv1 = tg[(s0 + 1) * 16 + jj];
    float4 sv1 = tg[(s0 + 1) * 16 + 8 + jj];

    // ---- stage-in: 32x64 floats, 16 LDG.128 -> 64 STS.32 (two batches) ----
    #pragma unroll
    for (int h = 0; h < 2; h++) {
        float4 v[8];
        #pragma unroll
        for (int it = 0; it < 8; it++)
            v[it] = gx4[l + 32 * (8 * h + it)];
        #pragma unroll
        for (int it = 0; it < 8; it++) {
            int q = l + 32 * (8 * h + it);
            int r = q >> 4;
            int c = (q & 15) * 4;
            float* p = &buf[r * PITCH + c + ((c >= 32) ? bpad(r & 3) : 0)];
            p[0] = v[it].x; p[1] = v[it].y; p[2] = v[it].z; p[3] = v[it].w;
        }
    }
    __syncwarp();

    // ---- Givens chain: lane l owns row l ----------------------------------
    {
        float* row = &buf[l * PITCH];
        const int p4 = l & 3;
        #pragma unroll
        for (int k = 0; k < NR_; k++) {
            float2 cs = scs[k];
            int pk = oij[k * 4 + p4];
            int oi = pk & 0xFFFF, oj = pk >> 16;
            float xi = row[oi];
            float xj = row[oj];
            row[oi] = fmaf(xi, cs.x, xj * cs.y);
            row[oj] = fmaf(xj, cs.x, -xi * cs.y);
        }
        // general path: dense r_matrix multiply (not taken when identity)
        if (!identity) {
            const int bp = bpad(p4);
            float y[HD_];
            for (int c2 = 0; c2 < HD_; c2++) {
                float acc = 0.0f;
                for (int k = 0; k < HD_; k++) {
                    int ow = k + ((k >= 32) ? bp : 0);
                    acc = fmaf(row[ow], __ldg(&r_matrix[k * HD_ + c2]), acc);
                }
                y[c2] = acc;
            }
            for (int c2 = 0; c2 < HD_; c2++)
                row[c2 + ((c2 >= 32) ? bp : 0)] = y[c2];
        }
    }
    __syncwarp();

    // ---- fused RoPE remix + coalesced stage-out ---------------------------
    // lane (jj, rslot) computes out[4jj..4jj+3] AND out[+32] for rows
    // r = rslot + 4i (row class == rslot; all banks distinct).
    {
        float4* o4 = (float4*)(out + (size_t)tile * (WROWS * HD_));
        #pragma unroll
        for (int i = 0; i < 8; i++) {
            int r = rslot + 4 * i;
            float4 cv = (i < 4) ? cv0 : cv1;             // s-group: r<16 ? 0 : 1
            float4 sv = (i < 4) ? sv0 : sv1;
            const float* row = &buf[r * PITCH + off0];
            float a0 = row[0], b0 = row[1];
            float a1 = row[2], b1 = row[3];
            float a2 = row[4], b2 = row[5];
            float a3 = row[6], b3 = row[7];
            float4 lo, hi;
            lo.x = a0 * cv.x - b0 * sv.x;  hi.x = a0 * sv.x + b0 * cv.x;
            lo.y = a1 * cv.y - b1 * sv.y;  hi.y = a1 * sv.y + b1 * cv.y;
            lo.z = a2 * cv.z - b2 * sv.z;  hi.z = a2 * sv.z + b2 * cv.z;
            lo.w = a3 * cv.w - b3 * sv.w;  hi.w = a3 * sv.w + b3 * cv.w;
            o4[r * 16 + jj]     = lo;
            o4[r * 16 + 8 + jj] = hi;
        }
    }
}

// ---------------------------------------------------------------------------
extern "C" void kernel_launch(void* const* d_in, const int* in_sizes, int n_in,
                              void* d_out, int out_size) {
    const float* x           = (const float*)d_in[0];
    const float* thetas      = (const float*)d_in[1];
    const float* r_pairs     = (const float*)d_in[2];
    const float* theta_scale = (const float*)d_in[3];
    // d_in[4] = n_rots_scale (unused by reference)
    const float* r_matrix    = (const float*)d_in[5];
    const float* inv_freq    = (const float*)d_in[6];
    float* out = (float*)d_out;

    table_kernel<<<(S_ * NR_ + 255) / 256, 256>>>(inv_freq);
    rotary_warp_kernel<<<NTILES / WARPS_PB, TPB>>>(x, thetas, r_pairs, theta_scale,
                                                   r_matrix, out);
}